// round 1
// baseline (speedup 1.0000x reference)
#include <cuda_runtime.h>
#include <cstdint>

#define BB 4
#define TT 4096
#define CC 1024
#define HH 64
constexpr int MROWS = BB * TT;  // 16384

// Scratch for projected q,k,v (device globals: no allocation allowed)
__device__ float g_q[MROWS * HH];
__device__ float g_k[MROWS * HH];
__device__ float g_v[MROWS * HH];

// ---------------- f32x2 packed-FMA helpers (Blackwell-only) ----------------
using u64 = unsigned long long;

__device__ __forceinline__ u64 pk2(float lo, float hi) {
    u64 r;
    asm("mov.b64 %0, {%1, %2};" : "=l"(r) : "f"(lo), "f"(hi));
    return r;
}
__device__ __forceinline__ void fma2(u64& d, u64 a, u64 b) {
    asm("fma.rn.f32x2 %0, %1, %2, %0;" : "+l"(d) : "l"(a), "l"(b));
}
__device__ __forceinline__ void mul2(u64& d, u64 a) {
    asm("mul.rn.f32x2 %0, %0, %1;" : "+l"(d) : "l"(a));
}
__device__ __forceinline__ float2 upk(u64 v) {
    float2 f;
    asm("mov.b64 {%0, %1}, %2;" : "=f"(f.x), "=f"(f.y) : "l"(v));
    return f;
}

// ---------------------------------------------------------------------------
// Kernel 1: fused QKV projection.  qkv[m, 0:192] = x[m, :] @ [Wq|Wk|Wv]
// GEMM M=16384, N=192, K=1024.  Block: 64 rows x 192 cols, 256 threads,
// thread tile 4 rows x 12 cols (6 f32x2 pairs).
// ---------------------------------------------------------------------------
__global__ __launch_bounds__(256) void proj_kernel(
    const float* __restrict__ x,
    const float* __restrict__ Wq,
    const float* __restrict__ Wk,
    const float* __restrict__ Wv)
{
    __shared__ float Xs[64][36];     // 64 rows x 32 k (pad to 36)
    __shared__ float Ws[32][196];    // 32 k x 192 n (pad to 196)

    const int tid = threadIdx.x;
    const int row0 = blockIdx.x * 64;
    const int rg = tid >> 4;   // 0..15  (rows rg*4 .. rg*4+3)
    const int cg = tid & 15;   // 0..15  (cols cg*12 .. cg*12+11)

    u64 acc[4][6];
#pragma unroll
    for (int i = 0; i < 4; i++)
#pragma unroll
        for (int j = 0; j < 6; j++) acc[i][j] = 0ull;

    for (int k0 = 0; k0 < CC; k0 += 32) {
        // load X chunk: 64 x 32 floats = 512 float4
#pragma unroll
        for (int e = 0; e < 2; e++) {
            int fid = tid + e * 256;
            int r = fid >> 3, kf = fid & 7;
            *(float4*)&Xs[r][kf * 4] =
                *(const float4*)&x[(size_t)(row0 + r) * CC + k0 + kf * 4];
        }
        // load W chunk: 32 x 192 floats = 1536 float4
#pragma unroll
        for (int e = 0; e < 6; e++) {
            int fid = tid + e * 256;
            int kk = fid / 48, nf = fid % 48;
            int n = nf * 4;
            int kg = k0 + kk;
            const float* src;
            if (n < 64)        src = &Wq[kg * 64 + n];
            else if (n < 128)  src = &Wk[kg * 64 + (n - 64)];
            else               src = &Wv[kg * 64 + (n - 128)];
            *(float4*)&Ws[kk][n] = *(const float4*)src;
        }
        __syncthreads();

#pragma unroll 8
        for (int kk = 0; kk < 32; kk++) {
            float xv[4];
#pragma unroll
            for (int i = 0; i < 4; i++) xv[i] = Xs[rg * 4 + i][kk];
            ulonglong2 w2[3];
            const ulonglong2* wrow = (const ulonglong2*)&Ws[kk][cg * 12];
#pragma unroll
            for (int j = 0; j < 3; j++) w2[j] = wrow[j];
#pragma unroll
            for (int i = 0; i < 4; i++) {
                u64 xp = pk2(xv[i], xv[i]);
                fma2(acc[i][0], xp, w2[0].x);
                fma2(acc[i][1], xp, w2[0].y);
                fma2(acc[i][2], xp, w2[1].x);
                fma2(acc[i][3], xp, w2[1].y);
                fma2(acc[i][4], xp, w2[2].x);
                fma2(acc[i][5], xp, w2[2].y);
            }
        }
        __syncthreads();
    }

    // store: route n<64 -> q, n<128 -> k, else v
#pragma unroll
    for (int i = 0; i < 4; i++) {
        int m = row0 + rg * 4 + i;
#pragma unroll
        for (int jj = 0; jj < 6; jj++) {
            float2 v = upk(acc[i][jj]);
            int n0 = cg * 12 + jj * 2;
#pragma unroll
            for (int e = 0; e < 2; e++) {
                int n = n0 + e;
                float val = (e == 0) ? v.x : v.y;
                if (n < 64)        g_q[(size_t)m * 64 + n] = val;
                else if (n < 128)  g_k[(size_t)m * 64 + (n - 64)] = val;
                else               g_v[(size_t)m * 64 + (n - 128)] = val;
            }
        }
    }
}

// ---------------------------------------------------------------------------
// Kernel 2: flash attention, causal.  BQ = BK = 64, head dim 64.
// 256 threads.  Online softmax; O accumulators in registers (f32x2 pairs).
// P is stored DUPLICATED (p,p) in smem so the PV phase can use f32x2 with a
// single LDS.64 broadcast operand (no pack MOVs in the hot loop).
// ---------------------------------------------------------------------------
#define LDSK 68   // row stride (floats) for Q/K/V tiles (64 + 4 pad)
#define LDSP 136  // row stride (floats) for duplicated P tile (128 + 8 pad)

__global__ __launch_bounds__(256) void attn_kernel(float* __restrict__ out)
{
    extern __shared__ float sm[];
    float* Qs  = sm;                  // 64*68
    float* Ks  = Qs + 64 * LDSK;      // 64*68
    float* Vs  = Ks + 64 * LDSK;      // 64*68
    float* Pd  = Vs + 64 * LDSK;      // 64*136 (duplicated P)
    float* mrow = Pd + 64 * LDSP;     // 64
    float* lrow = mrow + 64;          // 64
    float* arow = lrow + 64;          // 64

    const int tid = threadIdx.x;
    const int b   = blockIdx.y;
    const int qi  = (gridDim.x - 1) - blockIdx.x;  // longest blocks first
    const float scale = 0.03125f;  // 1024^-0.5 (reference scales by n_embd^-0.5)

    const int rg = tid >> 4;   // 0..15 : S/O rows  rg + 16*i
    const int cg = tid & 15;   // 0..15 : S cols cg + 16*j ; O cols cg*4..cg*4+3

    // load Q tile (scaled)
    const size_t qbase = ((size_t)b * TT + (size_t)qi * 64) * HH;
#pragma unroll
    for (int e = 0; e < 4; e++) {
        int fid = tid + e * 256;
        int r = fid >> 4, hf = fid & 15;
        float4 v = *(const float4*)&g_q[qbase + (size_t)r * 64 + hf * 4];
        v.x *= scale; v.y *= scale; v.z *= scale; v.w *= scale;
        *(float4*)&Qs[r * LDSK + hf * 4] = v;
    }
    if (tid < 64) { mrow[tid] = -1e30f; lrow[tid] = 0.f; }

    u64 o[4][2];
#pragma unroll
    for (int i = 0; i < 4; i++) { o[i][0] = 0ull; o[i][1] = 0ull; }

    const int srow = tid >> 2;   // softmax row (0..63)
    const int part = tid & 3;    // softmax quarter

    for (int kt = 0; kt <= qi; kt++) {
        __syncthreads();  // prev tile's phase-C reads done; Q load done (kt=0)

        const size_t kbase = ((size_t)b * TT + (size_t)kt * 64) * HH;
#pragma unroll
        for (int e = 0; e < 4; e++) {
            int fid = tid + e * 256;
            int r = fid >> 4, hf = fid & 15;
            *(float4*)&Ks[r * LDSK + hf * 4] =
                *(const float4*)&g_k[kbase + (size_t)r * 64 + hf * 4];
            *(float4*)&Vs[r * LDSK + hf * 4] =
                *(const float4*)&g_v[kbase + (size_t)r * 64 + hf * 4];
        }
        __syncthreads();

        // ---- Phase A: S = Q K^T (register tile 4x4, f32x2 over head dim) ----
        u64 s2[4][4];
#pragma unroll
        for (int i = 0; i < 4; i++)
#pragma unroll
            for (int j = 0; j < 4; j++) s2[i][j] = 0ull;

#pragma unroll 4
        for (int hg = 0; hg < 16; hg++) {
            ulonglong2 q2[4], k2[4];
#pragma unroll
            for (int i = 0; i < 4; i++)
                q2[i] = *(const ulonglong2*)&Qs[(rg + 16 * i) * LDSK + hg * 4];
#pragma unroll
            for (int j = 0; j < 4; j++)
                k2[j] = *(const ulonglong2*)&Ks[(cg + 16 * j) * LDSK + hg * 4];
#pragma unroll
            for (int i = 0; i < 4; i++)
#pragma unroll
                for (int j = 0; j < 4; j++) {
                    fma2(s2[i][j], q2[i].x, k2[j].x);
                    fma2(s2[i][j], q2[i].y, k2[j].y);
                }
        }
        const bool diag = (kt == qi);
#pragma unroll
        for (int i = 0; i < 4; i++) {
            int r_ = rg + 16 * i;
#pragma unroll
            for (int j = 0; j < 4; j++) {
                int c_ = cg + 16 * j;
                float2 p = upk(s2[i][j]);
                float s = p.x + p.y;
                if (diag && c_ > r_) s = -1e30f;
                Pd[r_ * LDSP + 2 * c_] = s;
            }
        }
        __syncthreads();

        // ---- Phase B: online softmax (4 threads per row) ----
        {
            float vals[16];
#pragma unroll
            for (int e = 0; e < 16; e++)
                vals[e] = Pd[srow * LDSP + 2 * (part * 16 + e)];
            float mt = vals[0];
#pragma unroll
            for (int e = 1; e < 16; e++) mt = fmaxf(mt, vals[e]);
            mt = fmaxf(mt, __shfl_xor_sync(0xffffffffu, mt, 1));
            mt = fmaxf(mt, __shfl_xor_sync(0xffffffffu, mt, 2));
            float mold = mrow[srow];
            float mnew = fmaxf(mold, mt);
            float sum = 0.f;
#pragma unroll
            for (int e = 0; e < 16; e++) {
                float p = __expf(vals[e] - mnew);
                sum += p;
                *(u64*)&Pd[srow * LDSP + 2 * (part * 16 + e)] = pk2(p, p);
            }
            sum += __shfl_xor_sync(0xffffffffu, sum, 1);
            sum += __shfl_xor_sync(0xffffffffu, sum, 2);
            if (part == 0) {
                float alpha = __expf(mold - mnew);
                lrow[srow] = lrow[srow] * alpha + sum;
                mrow[srow] = mnew;
                arow[srow] = alpha;
            }
        }
        __syncthreads();

        // ---- Phase C: O = O*alpha + P V (f32x2 over output cols) ----
#pragma unroll
        for (int i = 0; i < 4; i++) {
            float a = arow[rg + 16 * i];
            u64 ap = pk2(a, a);
            mul2(o[i][0], ap);
            mul2(o[i][1], ap);
        }
#pragma unroll 4
        for (int sg = 0; sg < 16; sg++) {
            ulonglong2 v2[4];
#pragma unroll
            for (int ss = 0; ss < 4; ss++)
                v2[ss] = *(const ulonglong2*)&Vs[(sg * 4 + ss) * LDSK + cg * 4];
#pragma unroll
            for (int i = 0; i < 4; i++) {
                const float* prow = &Pd[(rg + 16 * i) * LDSP];
#pragma unroll
                for (int ss = 0; ss < 4; ss++) {
                    u64 p = *(const u64*)&prow[2 * (sg * 4 + ss)];
                    fma2(o[i][0], p, v2[ss].x);
                    fma2(o[i][1], p, v2[ss].y);
                }
            }
        }
    }

    // ---- epilogue: divide by l, store ----
#pragma unroll
    for (int i = 0; i < 4; i++) {
        int r_ = rg + 16 * i;
        float inv = 1.f / lrow[r_];
        float2 a = upk(o[i][0]);
        float2 c = upk(o[i][1]);
        float4 res;
        res.x = a.x * inv; res.y = a.y * inv;
        res.z = c.x * inv; res.w = c.y * inv;
        *(float4*)&out[(((size_t)b * TT + (size_t)qi * 64 + r_) * HH) + cg * 4] = res;
    }
}

// ---------------------------------------------------------------------------
extern "C" void kernel_launch(void* const* d_in, const int* in_sizes, int n_in,
                              void* d_out, int out_size)
{
    const float* x  = (const float*)d_in[0];
    const float* Wq = (const float*)d_in[1];
    const float* Wk = (const float*)d_in[2];
    const float* Wv = (const float*)d_in[3];
    float* out = (float*)d_out;

    const int attn_smem = (3 * 64 * LDSK + 64 * LDSP + 192) * (int)sizeof(float); // 87808
    cudaFuncSetAttribute(attn_kernel,
                         cudaFuncAttributeMaxDynamicSharedMemorySize, attn_smem);

    proj_kernel<<<MROWS / 64, 256>>>(x, Wq, Wk, Wv);
    attn_kernel<<<dim3(TT / 64, BB), 256, attn_smem>>>(out);
}